// round 1
// baseline (speedup 1.0000x reference)
#include <cuda_runtime.h>
#include <math.h>

#define NNODES 65536   // nodes per branch (B*S)
#define NB     8192    // graph blocks
#define SS     8       // nodes per block
#define EPB    64      // edges per block
#define DIN    512
#define DOUT   256

// ---- scratch (static device globals; no allocation allowed) ----
__device__ float g_xw[2ULL * NNODES * DOUT];   // 128 MB: xw for pos then neg
__device__ float g_pos_pool[NB * DOUT];
__device__ float g_neg_pool[NB * DOUT];
__device__ float g_anchor[NB * DOUT];
__device__ float g_T[NB * DOUT];

// ======================= GEMM1: X @ W_gcn =======================
// M = 2*NNODES (pos rows then neg rows), K = 512, N = 256
#define BM 128
#define BN 64
#define BK 16

__global__ __launch_bounds__(256) void gemm1_kernel(
    const float* __restrict__ posx, const float* __restrict__ negx,
    const float* __restrict__ Wg)
{
    __shared__ float As[BK][BM];
    __shared__ float Bs[BK][BN];

    const int tid = threadIdx.x;
    const int m0 = blockIdx.x * BM;
    const int n0 = blockIdx.y * BN;
    // BM=128 divides NNODES, so a CTA never straddles the pos/neg boundary
    const float* X = (m0 < NNODES) ? (posx + (size_t)m0 * DIN)
                                   : (negx + (size_t)(m0 - NNODES) * DIN);

    const int ar = tid >> 2;          // 0..63 (A row base, +64 for 2nd chunk)
    const int ac = (tid & 3) << 2;    // 0,4,8,12 (A k-chunk)
    const int br = tid >> 4;          // 0..15 (B k row)
    const int bc = (tid & 15) << 2;   // 0..60 (B n chunk)
    const int ty = tid >> 4;          // 0..15 -> 8 M rows
    const int tx = tid & 15;          // 0..15 -> 4 N cols

    float acc[8][4];
    #pragma unroll
    for (int i = 0; i < 8; i++)
        #pragma unroll
        for (int j = 0; j < 4; j++) acc[i][j] = 0.f;

    for (int k0 = 0; k0 < DIN; k0 += BK) {
        #pragma unroll
        for (int c = 0; c < 2; c++) {
            int row = ar + c * 64;
            float4 v = *(const float4*)(X + (size_t)row * DIN + k0 + ac);
            As[ac + 0][row] = v.x;
            As[ac + 1][row] = v.y;
            As[ac + 2][row] = v.z;
            As[ac + 3][row] = v.w;
        }
        {
            float4 v = *(const float4*)(Wg + (size_t)(k0 + br) * DOUT + n0 + bc);
            *(float4*)&Bs[br][bc] = v;
        }
        __syncthreads();

        #pragma unroll
        for (int k = 0; k < BK; k++) {
            float a[8], bb[4];
            #pragma unroll
            for (int i = 0; i < 8; i++) a[i] = As[k][ty * 8 + i];
            #pragma unroll
            for (int j = 0; j < 4; j++) bb[j] = Bs[k][tx * 4 + j];
            #pragma unroll
            for (int i = 0; i < 8; i++)
                #pragma unroll
                for (int j = 0; j < 4; j++)
                    acc[i][j] = fmaf(a[i], bb[j], acc[i][j]);
        }
        __syncthreads();
    }

    #pragma unroll
    for (int i = 0; i < 8; i++) {
        int row = m0 + ty * 8 + i;
        float4 v = make_float4(acc[i][0], acc[i][1], acc[i][2], acc[i][3]);
        *(float4*)&g_xw[(size_t)row * DOUT + n0 + tx * 4] = v;
    }
}

// ============== fused aggregate + PReLU + pool + L2norm =============
// One CTA per graph block. 256 threads, thread j owns feature column j.
__global__ __launch_bounds__(256) void agg_kernel(
    int is_pos,
    const int* __restrict__ src, const int* __restrict__ dst,
    const float* __restrict__ w,
    const float* __restrict__ b_gcn, const float* __restrict__ prelu_a)
{
    const int b = blockIdx.x;
    const int j = threadIdx.x;

    __shared__ float xs[SS][DOUT];
    __shared__ float as_[SS][DOUT];
    __shared__ int   es[EPB];
    __shared__ int   ed[EPB];
    __shared__ float ew[EPB];
    __shared__ float redp[8], reda[8];

    const int node_off = is_pos ? 0 : NNODES;
    const float* xwb = g_xw + ((size_t)(node_off + b * SS)) * DOUT;

    #pragma unroll
    for (int r = 0; r < SS; r++) {
        xs[r][j]  = xwb[(size_t)r * DOUT + j];
        as_[r][j] = 0.f;
    }
    if (j < EPB) {
        int e = b * EPB + j;
        es[j] = src[e] & (SS - 1);   // block-local src
        ed[j] = dst[e] & (SS - 1);   // block-local dst
        ew[j] = w[e];
    }
    __syncthreads();

    // per-thread column: no races, no atomics
    #pragma unroll 8
    for (int e = 0; e < EPB; e++)
        as_[ed[e]][j] += ew[e] * xs[es[e]][j];

    const float pa = prelu_a[0];
    const float bj = b_gcn[j];
    float pool = 0.f, anchor = 0.f;
    #pragma unroll
    for (int r = 0; r < SS; r++) {
        float h = as_[r][j] + bj;
        h = (h >= 0.f) ? h : pa * h;
        if (r < SS - 1) pool += h;
        else            anchor = h;
    }
    pool *= (1.0f / (float)(SS - 1));

    // block reduction of squared norms (two at once)
    float vp = pool * pool, va = anchor * anchor;
    #pragma unroll
    for (int o = 16; o; o >>= 1) {
        vp += __shfl_xor_sync(0xffffffffu, vp, o);
        va += __shfl_xor_sync(0xffffffffu, va, o);
    }
    const int lane = j & 31, wrp = j >> 5;
    if (lane == 0) { redp[wrp] = vp; reda[wrp] = va; }
    __syncthreads();
    float sp = 0.f, sa = 0.f;
    #pragma unroll
    for (int i = 0; i < 8; i++) { sp += redp[i]; sa += reda[i]; }

    const float inp = 1.f / fmaxf(sqrtf(sp), 1e-12f);
    const float ina = 1.f / fmaxf(sqrtf(sa), 1e-12f);

    if (is_pos) {
        g_pos_pool[(size_t)b * DOUT + j] = pool * inp;
        g_anchor[(size_t)b * DOUT + j]   = anchor * ina;
    } else {
        g_neg_pool[(size_t)b * DOUT + j] = pool * inp;
    }
}

// ================= GEMM2: T = anchor @ W_bil^T ==================
// M = NB(8192), K = 256, N = 256.  B operand: Bs[k][n] = W_bil[n*256 + k]
__global__ __launch_bounds__(256) void gemm2_kernel(const float* __restrict__ Wb)
{
    __shared__ float As[BK][BM];
    __shared__ float Bs[BK][BN];

    const int tid = threadIdx.x;
    const int m0 = blockIdx.x * BM;
    const int n0 = blockIdx.y * BN;

    const int ar = tid >> 2;
    const int ac = (tid & 3) << 2;
    const int bn_ = tid >> 2;          // 0..63 (n index)
    const int bkc = (tid & 3) << 2;    // k chunk
    const int ty = tid >> 4;
    const int tx = tid & 15;

    float acc[8][4];
    #pragma unroll
    for (int i = 0; i < 8; i++)
        #pragma unroll
        for (int j = 0; j < 4; j++) acc[i][j] = 0.f;

    for (int k0 = 0; k0 < DOUT; k0 += BK) {
        #pragma unroll
        for (int c = 0; c < 2; c++) {
            int row = ar + c * 64;
            float4 v = *(const float4*)(&g_anchor[(size_t)(m0 + row) * DOUT + k0 + ac]);
            As[ac + 0][row] = v.x;
            As[ac + 1][row] = v.y;
            As[ac + 2][row] = v.z;
            As[ac + 3][row] = v.w;
        }
        {
            float4 v = *(const float4*)(Wb + (size_t)(n0 + bn_) * DOUT + k0 + bkc);
            Bs[bkc + 0][bn_] = v.x;
            Bs[bkc + 1][bn_] = v.y;
            Bs[bkc + 2][bn_] = v.z;
            Bs[bkc + 3][bn_] = v.w;
        }
        __syncthreads();

        #pragma unroll
        for (int k = 0; k < BK; k++) {
            float a[8], bb[4];
            #pragma unroll
            for (int i = 0; i < 8; i++) a[i] = As[k][ty * 8 + i];
            #pragma unroll
            for (int j = 0; j < 4; j++) bb[j] = Bs[k][tx * 4 + j];
            #pragma unroll
            for (int i = 0; i < 8; i++)
                #pragma unroll
                for (int j = 0; j < 4; j++)
                    acc[i][j] = fmaf(a[i], bb[j], acc[i][j]);
        }
        __syncthreads();
    }

    #pragma unroll
    for (int i = 0; i < 8; i++) {
        int row = m0 + ty * 8 + i;
        float4 v = make_float4(acc[i][0], acc[i][1], acc[i][2], acc[i][3]);
        *(float4*)&g_T[(size_t)row * DOUT + n0 + tx * 4] = v;
    }
}

// ============ final scores: rowwise dots + bias ============
__global__ __launch_bounds__(256) void score_kernel(
    const float* __restrict__ b_bil, float* __restrict__ out)
{
    const int gwarp = (blockIdx.x * blockDim.x + threadIdx.x) >> 5;
    const int lane = threadIdx.x & 31;
    if (gwarp >= NB) return;

    float sp = 0.f, sn = 0.f;
    #pragma unroll
    for (int i = lane; i < DOUT; i += 32) {
        float t = g_T[(size_t)gwarp * DOUT + i];
        sp += g_pos_pool[(size_t)gwarp * DOUT + i] * t;
        sn += g_neg_pool[(size_t)gwarp * DOUT + i] * t;
    }
    #pragma unroll
    for (int o = 16; o; o >>= 1) {
        sp += __shfl_xor_sync(0xffffffffu, sp, o);
        sn += __shfl_xor_sync(0xffffffffu, sn, o);
    }
    if (lane == 0) {
        float bb = b_bil[0];
        out[gwarp]      = sp + bb;
        out[NB + gwarp] = sn + bb;
    }
}

extern "C" void kernel_launch(void* const* d_in, const int* in_sizes, int n_in,
                              void* d_out, int out_size)
{
    const float* pos_x   = (const float*)d_in[0];
    const float* neg_x   = (const float*)d_in[1];
    const int*   pos_src = (const int*)d_in[2];
    const int*   pos_dst = (const int*)d_in[3];
    const float* pos_w   = (const float*)d_in[4];
    const int*   neg_src = (const int*)d_in[5];
    const int*   neg_dst = (const int*)d_in[6];
    const float* neg_w   = (const float*)d_in[7];
    const float* W_gcn   = (const float*)d_in[8];
    const float* b_gcn   = (const float*)d_in[9];
    const float* prelu_a = (const float*)d_in[10];
    const float* W_bil   = (const float*)d_in[11];
    const float* b_bil   = (const float*)d_in[12];
    float* out = (float*)d_out;

    (void)in_sizes; (void)n_in; (void)out_size;

    // 1) xw = [pos_x; neg_x] @ W_gcn
    gemm1_kernel<<<dim3(2 * NNODES / BM, DOUT / BN), 256>>>(pos_x, neg_x, W_gcn);

    // 2) per-block scatter-add + PReLU + mean-pool + anchor + L2 norm
    agg_kernel<<<NB, 256>>>(1, pos_src, pos_dst, pos_w, b_gcn, prelu_a);
    agg_kernel<<<NB, 256>>>(0, neg_src, neg_dst, neg_w, b_gcn, prelu_a);

    // 3) T = anchor @ W_bil^T
    gemm2_kernel<<<dim3(NB / BM, DOUT / BN), 256>>>(W_bil);

    // 4) scores
    score_kernel<<<(NB * 32) / 256, 256>>>(b_bil, out);
}

// round 3
// speedup vs baseline: 1.6281x; 1.6281x over previous
#include <cuda_runtime.h>
#include <cuda_bf16.h>
#include <cstdint>
#include <math.h>

#define NNODES 65536   // nodes per branch (B*S)
#define NB     8192    // graph blocks
#define SS     8       // nodes per block
#define EPB    64      // edges per block
#define DIN    512
#define DOUT   256

// ---- scratch (static device globals; no allocation allowed) ----
__device__ float g_xw[2ULL * NNODES * DOUT];
__device__ float g_pos_pool[NB * DOUT];
__device__ float g_neg_pool[NB * DOUT];
__device__ float g_anchor[NB * DOUT];
__device__ float g_T[NB * DOUT];
__device__ __nv_bfloat16 g_wt_hi[DOUT * DIN];  // W_gcn^T split-hi [256][512]
__device__ __nv_bfloat16 g_wt_lo[DOUT * DIN];  // W_gcn^T split-lo

// ======================= helpers =======================
__device__ __forceinline__ uint32_t smem_u32(const void* p) {
    uint32_t a;
    asm("{ .reg .u64 t; cvta.to.shared.u64 t, %1; cvt.u32.u64 %0, t; }"
        : "=r"(a) : "l"(p));
    return a;
}

#define LDSM_X4(r0, r1, r2, r3, addr) \
    asm volatile("ldmatrix.sync.aligned.m8n8.x4.shared.b16 {%0,%1,%2,%3}, [%4];" \
        : "=r"(r0), "=r"(r1), "=r"(r2), "=r"(r3) : "r"(addr))

#define MMA16816(d, a, b0, b1) \
    asm volatile("mma.sync.aligned.m16n8k16.row.col.f32.bf16.bf16.f32 " \
        "{%0,%1,%2,%3}, {%4,%5,%6,%7}, {%8,%9}, {%0,%1,%2,%3};" \
        : "+f"((d)[0]), "+f"((d)[1]), "+f"((d)[2]), "+f"((d)[3]) \
        : "r"((a)[0]), "r"((a)[1]), "r"((a)[2]), "r"((a)[3]), "r"(b0), "r"(b1))

__device__ __forceinline__ void split2(float x0, float x1, uint32_t& h, uint32_t& l) {
    __nv_bfloat16 h0 = __float2bfloat16(x0);
    __nv_bfloat16 h1 = __float2bfloat16(x1);
    __nv_bfloat16 l0 = __float2bfloat16(x0 - __bfloat162float(h0));
    __nv_bfloat16 l1 = __float2bfloat16(x1 - __bfloat162float(h1));
    __nv_bfloat162 hh = __halves2bfloat162(h0, h1);
    __nv_bfloat162 ll = __halves2bfloat162(l0, l1);
    h = *reinterpret_cast<uint32_t*>(&hh);
    l = *reinterpret_cast<uint32_t*>(&ll);
}

// ============ W_gcn split + transpose: [512][256] f32 -> [256][512] bf16 x2 ======
__global__ __launch_bounds__(256) void wsplit_kernel(const float* __restrict__ Wg)
{
    int idx = blockIdx.x * 256 + threadIdx.x;   // grid 512 -> 131072 elems
    int k = idx >> 8;
    int n = idx & 255;
    float x = Wg[idx];
    __nv_bfloat16 h = __float2bfloat16(x);
    __nv_bfloat16 l = __float2bfloat16(x - __bfloat162float(h));
    g_wt_hi[(size_t)n * DIN + k] = h;
    g_wt_lo[(size_t)n * DIN + k] = l;
}

// ======================= GEMM1 (mma.sync bf16, 3-term split) =======================
// CTA tile 128x128, K=512 in 16 chunks of 32. 8 warps, warp tile 32x64.
// smem rows padded to 80B: row offsets mod 128 are 8 distinct multiples of 16
// -> ldmatrix conflict-free without swizzle.
#define RPAD 80

__global__ __launch_bounds__(256, 2) void gemm1_mma(
    const float* __restrict__ posx, const float* __restrict__ negx)
{
    __shared__ __align__(16) char sAhi[128 * RPAD];
    __shared__ __align__(16) char sAlo[128 * RPAD];
    __shared__ __align__(16) char sBhi[128 * RPAD];
    __shared__ __align__(16) char sBlo[128 * RPAD];

    const int tid = threadIdx.x;
    const int wid = tid >> 5;
    const int lane = tid & 31;

    const int m0 = blockIdx.x * 128;     // 128 | 65536 -> never straddles pos/neg
    const int n0 = blockIdx.y * 128;
    const int warp_m = (wid & 3) * 32;
    const int warp_n = (wid >> 2) * 64;

    const float* X = (m0 < NNODES) ? (posx + (size_t)m0 * DIN)
                                   : (negx + (size_t)(m0 - NNODES) * DIN);

    const uint32_t ahi_b = smem_u32(sAhi);
    const uint32_t alo_b = smem_u32(sAlo);
    const uint32_t bhi_b = smem_u32(sBhi);
    const uint32_t blo_b = smem_u32(sBlo);

    // loader mapping: thread t -> row t>>1, 32B half-row (chunks lc, lc+1)
    const int lrow = tid >> 1;
    const int lc   = (tid & 1) * 2;        // 16B-chunk base: 0 or 2
    const uint32_t st_off = (uint32_t)lrow * RPAD + (uint32_t)lc * 16;

    // ldmatrix lane addressing (A): lanes 0-15 rows, 16-31 rows with k+8
    const int a_r  = lane & 15;
    const int a_cg = lane >> 4;            // 0/1 -> k offset 0/8
    // ldmatrix lane addressing (B): tiles (n-major rows)
    const int b_t  = lane >> 3;
    const int b_r  = lane & 7;
    const int b_nn = ((b_t >> 1) << 3) + b_r;   // 0..15 within a 16-n group
    const int b_kk = (b_t & 1) << 3;            // 0/8

    float acc[2][8][4];
    #pragma unroll
    for (int i = 0; i < 2; i++)
        #pragma unroll
        for (int j = 0; j < 8; j++)
            #pragma unroll
            for (int q = 0; q < 4; q++) acc[i][j][q] = 0.f;

    for (int kt = 0; kt < DIN / 32; kt++) {
        const int k0 = kt * 32;

        // ---- load A (fp32 -> hi/lo bf16 split) ----
        {
            const float* ap = X + (size_t)lrow * DIN + k0 + lc * 8;
            float4 v0 = *(const float4*)(ap + 0);
            float4 v1 = *(const float4*)(ap + 4);
            float4 v2 = *(const float4*)(ap + 8);
            float4 v3 = *(const float4*)(ap + 12);
            uint32_t h[8], l[8];
            split2(v0.x, v0.y, h[0], l[0]);
            split2(v0.z, v0.w, h[1], l[1]);
            split2(v1.x, v1.y, h[2], l[2]);
            split2(v1.z, v1.w, h[3], l[3]);
            split2(v2.x, v2.y, h[4], l[4]);
            split2(v2.z, v2.w, h[5], l[5]);
            split2(v3.x, v3.y, h[6], l[6]);
            split2(v3.z, v3.w, h[7], l[7]);
            *(uint4*)(sAhi + st_off)      = make_uint4(h[0], h[1], h[2], h[3]);
            *(uint4*)(sAhi + st_off + 16) = make_uint4(h[4], h[5], h[6], h[7]);
            *(uint4*)(sAlo + st_off)      = make_uint4(l[0], l[1], l[2], l[3]);
            *(uint4*)(sAlo + st_off + 16) = make_uint4(l[4], l[5], l[6], l[7]);
        }
        // ---- load B (pre-split bf16, [n][k] rows) ----
        {
            const char* bh = (const char*)(g_wt_hi + (size_t)(n0 + lrow) * DIN + k0 + lc * 8);
            const char* bl = (const char*)(g_wt_lo + (size_t)(n0 + lrow) * DIN + k0 + lc * 8);
            uint4 h0 = *(const uint4*)(bh);
            uint4 h1 = *(const uint4*)(bh + 16);
            uint4 l0 = *(const uint4*)(bl);
            uint4 l1 = *(const uint4*)(bl + 16);
            *(uint4*)(sBhi + st_off)      = h0;
            *(uint4*)(sBhi + st_off + 16) = h1;
            *(uint4*)(sBlo + st_off)      = l0;
            *(uint4*)(sBlo + st_off + 16) = l1;
        }
        __syncthreads();

        // ---- compute: 2 k16 steps, 3 split terms ----
        #pragma unroll
        for (int k16 = 0; k16 < 32; k16 += 16) {
            uint32_t ahi[2][4], alo[2][4];
            const uint32_t a_off = (uint32_t)(warp_m + a_r) * RPAD
                                 + (uint32_t)(k16 + a_cg * 8) * 2;
            LDSM_X4(ahi[0][0], ahi[0][1], ahi[0][2], ahi[0][3], ahi_b + a_off);
            LDSM_X4(ahi[1][0], ahi[1][1], ahi[1][2], ahi[1][3], ahi_b + a_off + 16 * RPAD);
            LDSM_X4(alo[0][0], alo[0][1], alo[0][2], alo[0][3], alo_b + a_off);
            LDSM_X4(alo[1][0], alo[1][1], alo[1][2], alo[1][3], alo_b + a_off + 16 * RPAD);

            #pragma unroll
            for (int g = 0; g < 4; g++) {   // 4 groups of 16 n-cols
                const uint32_t b_off = (uint32_t)(warp_n + g * 16 + b_nn) * RPAD
                                     + (uint32_t)(k16 + b_kk) * 2;
                uint32_t bh[4], bl[4];
                LDSM_X4(bh[0], bh[1], bh[2], bh[3], bhi_b + b_off);
                LDSM_X4(bl[0], bl[1], bl[2], bl[3], blo_b + b_off);
                #pragma unroll
                for (int mi = 0; mi < 2; mi++) {
                    MMA16816(acc[mi][g * 2 + 0], ahi[mi], bh[0], bh[1]);
                    MMA16816(acc[mi][g * 2 + 1], ahi[mi], bh[2], bh[3]);
                    MMA16816(acc[mi][g * 2 + 0], alo[mi], bh[0], bh[1]);
                    MMA16816(acc[mi][g * 2 + 1], alo[mi], bh[2], bh[3]);
                    MMA16816(acc[mi][g * 2 + 0], ahi[mi], bl[0], bl[1]);
                    MMA16816(acc[mi][g * 2 + 1], ahi[mi], bl[2], bl[3]);
                }
            }
        }
        __syncthreads();
    }

    // ---- epilogue: write accumulators to g_xw ----
    const int er = lane >> 2;            // 0..7
    const int ec = (lane & 3) * 2;       // 0,2,4,6
    #pragma unroll
    for (int mi = 0; mi < 2; mi++) {
        #pragma unroll
        for (int nf = 0; nf < 8; nf++) {
            int row = m0 + warp_m + mi * 16 + er;
            int col = n0 + warp_n + nf * 8 + ec;
            float* p0 = g_xw + (size_t)row * DOUT + col;
            float* p1 = g_xw + (size_t)(row + 8) * DOUT + col;
            p0[0] = acc[mi][nf][0];
            p0[1] = acc[mi][nf][1];
            p1[0] = acc[mi][nf][2];
            p1[1] = acc[mi][nf][3];
        }
    }
}

// ============== fused aggregate + PReLU + pool + L2norm =============
__global__ __launch_bounds__(256) void agg_kernel(
    int is_pos,
    const int* __restrict__ src, const int* __restrict__ dst,
    const float* __restrict__ w,
    const float* __restrict__ b_gcn, const float* __restrict__ prelu_a)
{
    const int b = blockIdx.x;
    const int j = threadIdx.x;

    __shared__ float xs[SS][DOUT];
    __shared__ float as_[SS][DOUT];
    __shared__ int   es[EPB];
    __shared__ int   ed[EPB];
    __shared__ float ew[EPB];
    __shared__ float redp[8], reda[8];

    const int node_off = is_pos ? 0 : NNODES;
    const float* xwb = g_xw + ((size_t)(node_off + b * SS)) * DOUT;

    #pragma unroll
    for (int r = 0; r < SS; r++) {
        xs[r][j]  = xwb[(size_t)r * DOUT + j];
        as_[r][j] = 0.f;
    }
    if (j < EPB) {
        int e = b * EPB + j;
        es[j] = src[e] & (SS - 1);
        ed[j] = dst[e] & (SS - 1);
        ew[j] = w[e];
    }
    __syncthreads();

    #pragma unroll 8
    for (int e = 0; e < EPB; e++)
        as_[ed[e]][j] += ew[e] * xs[es[e]][j];

    const float pa = prelu_a[0];
    const float bj = b_gcn[j];
    float pool = 0.f, anchor = 0.f;
    #pragma unroll
    for (int r = 0; r < SS; r++) {
        float h = as_[r][j] + bj;
        h = (h >= 0.f) ? h : pa * h;
        if (r < SS - 1) pool += h;
        else            anchor = h;
    }
    pool *= (1.0f / (float)(SS - 1));

    float vp = pool * pool, va = anchor * anchor;
    #pragma unroll
    for (int o = 16; o; o >>= 1) {
        vp += __shfl_xor_sync(0xffffffffu, vp, o);
        va += __shfl_xor_sync(0xffffffffu, va, o);
    }
    const int lane = j & 31, wrp = j >> 5;
    if (lane == 0) { redp[wrp] = vp; reda[wrp] = va; }
    __syncthreads();
    float sp = 0.f, sa = 0.f;
    #pragma unroll
    for (int i = 0; i < 8; i++) { sp += redp[i]; sa += reda[i]; }

    const float inp = 1.f / fmaxf(sqrtf(sp), 1e-12f);
    const float ina = 1.f / fmaxf(sqrtf(sa), 1e-12f);

    if (is_pos) {
        g_pos_pool[(size_t)b * DOUT + j] = pool * inp;
        g_anchor[(size_t)b * DOUT + j]   = anchor * ina;
    } else {
        g_neg_pool[(size_t)b * DOUT + j] = pool * inp;
    }
}

// ================= GEMM2: T = anchor @ W_bil^T (fp32 SIMT) ==================
#define BM 128
#define BN 64
#define BK 16

__global__ __launch_bounds__(256) void gemm2_kernel(const float* __restrict__ Wb)
{
    __shared__ float As[BK][BM];
    __shared__ float Bs[BK][BN];

    const int tid = threadIdx.x;
    const int m0 = blockIdx.x * BM;
    const int n0 = blockIdx.y * BN;

    const int ar = tid >> 2;
    const int ac = (tid & 3) << 2;
    const int bn_ = tid >> 2;
    const int bkc = (tid & 3) << 2;
    const int ty = tid >> 4;
    const int tx = tid & 15;

    float acc[8][4];
    #pragma unroll
    for (int i = 0; i < 8; i++)
        #pragma unroll
        for (int j = 0; j < 4; j++) acc[i][j] = 0.f;

    for (int k0 = 0; k0 < DOUT; k0 += BK) {
        #pragma unroll
        for (int c = 0; c < 2; c++) {
            int row = ar + c * 64;
            float4 v = *(const float4*)(&g_anchor[(size_t)(m0 + row) * DOUT + k0 + ac]);
            As[ac + 0][row] = v.x;
            As[ac + 1][row] = v.y;
            As[ac + 2][row] = v.z;
            As[ac + 3][row] = v.w;
        }
        {
            float4 v = *(const float4*)(Wb + (size_t)(n0 + bn_) * DOUT + k0 + bkc);
            Bs[bkc + 0][bn_] = v.x;
            Bs[bkc + 1][bn_] = v.y;
            Bs[bkc + 2][bn_] = v.z;
            Bs[bkc + 3][bn_] = v.w;
        }
        __syncthreads();

        #pragma unroll
        for (int k = 0; k < BK; k++) {
            float a[8], bb[4];
            #pragma unroll
            for (int i = 0; i < 8; i++) a[i] = As[k][ty * 8 + i];
            #pragma unroll
            for (int j = 0; j < 4; j++) bb[j] = Bs[k][tx * 4 + j];
            #pragma unroll
            for (int i = 0; i < 8; i++)
                #pragma unroll
                for (int j = 0; j < 4; j++)
                    acc[i][j] = fmaf(a[i], bb[j], acc[i][j]);
        }
        __syncthreads();
    }

    #pragma unroll
    for (int i = 0; i < 8; i++) {
        int row = m0 + ty * 8 + i;
        float4 v = make_float4(acc[i][0], acc[i][1], acc[i][2], acc[i][3]);
        *(float4*)&g_T[(size_t)row * DOUT + n0 + tx * 4] = v;
    }
}

// ============ final scores: rowwise dots + bias ============
__global__ __launch_bounds__(256) void score_kernel(
    const float* __restrict__ b_bil, float* __restrict__ out)
{
    const int gwarp = (blockIdx.x * blockDim.x + threadIdx.x) >> 5;
    const int lane = threadIdx.x & 31;
    if (gwarp >= NB) return;

    float sp = 0.f, sn = 0.f;
    #pragma unroll
    for (int i = lane; i < DOUT; i += 32) {
        float t = g_T[(size_t)gwarp * DOUT + i];
        sp += g_pos_pool[(size_t)gwarp * DOUT + i] * t;
        sn += g_neg_pool[(size_t)gwarp * DOUT + i] * t;
    }
    #pragma unroll
    for (int o = 16; o; o >>= 1) {
        sp += __shfl_xor_sync(0xffffffffu, sp, o);
        sn += __shfl_xor_sync(0xffffffffu, sn, o);
    }
    if (lane == 0) {
        float bb = b_bil[0];
        out[gwarp]      = sp + bb;
        out[NB + gwarp] = sn + bb;
    }
}

extern "C" void kernel_launch(void* const* d_in, const int* in_sizes, int n_in,
                              void* d_out, int out_size)
{
    const float* pos_x   = (const float*)d_in[0];
    const float* neg_x   = (const float*)d_in[1];
    const int*   pos_src = (const int*)d_in[2];
    const int*   pos_dst = (const int*)d_in[3];
    const float* pos_w   = (const float*)d_in[4];
    const int*   neg_src = (const int*)d_in[5];
    const int*   neg_dst = (const int*)d_in[6];
    const float* neg_w   = (const float*)d_in[7];
    const float* W_gcn   = (const float*)d_in[8];
    const float* b_gcn   = (const float*)d_in[9];
    const float* prelu_a = (const float*)d_in[10];
    const float* W_bil   = (const float*)d_in[11];
    const float* b_bil   = (const float*)d_in[12];
    float* out = (float*)d_out;

    (void)in_sizes; (void)n_in; (void)out_size;

    // 0) split+transpose W_gcn into bf16 hi/lo
    wsplit_kernel<<<512, 256>>>(W_gcn);

    // 1) xw = [pos_x; neg_x] @ W_gcn via mma.sync bf16 (3-term split)
    gemm1_mma<<<dim3(2 * NNODES / 128, DOUT / 128), 256>>>(pos_x, neg_x);

    // 2) per-block scatter-add + PReLU + mean-pool + anchor + L2 norm
    agg_kernel<<<NB, 256>>>(1, pos_src, pos_dst, pos_w, b_gcn, prelu_a);
    agg_kernel<<<NB, 256>>>(0, neg_src, neg_dst, neg_w, b_gcn, prelu_a);

    // 3) T = anchor @ W_bil^T
    gemm2_kernel<<<dim3(NB / BM, DOUT / BN), 256>>>(W_bil);

    // 4) scores
    score_kernel<<<(NB * 32) / 256, 256>>>(b_bil, out);
}